// round 14
// baseline (speedup 1.0000x reference)
#include <cuda_runtime.h>
#include <cstdint>

// RBDispatcher — R12: single-variable experiment = store cache policy.
// Identical to R7 (best kernel, 41.6us: 2 rows/CTA, batched loads, adjacent
// dedup) but with DEFAULT stores instead of __stcs (evict-first).
//
//   out[r]        = x[ idx_s1[ s1_to_s2[r] ] / TOP_K ]   r in [0, N_S2)
//   out[N_S2 + i] = x[ idx_s1[i] / TOP_K ]               i in [0, N_S1)
//
// Context: R3/R4/R5/R7/R11 (all __stcs) are schedule-invariant at
// 41.6-42.6us, ~4.8TB/s of DRAM writes, DRAM active only 67%. The store
// policy is the one variable never tested. If default stores regress
// (predicted: output evicts x from L2 -> +reads, ~47us), R7's model is
// confirmed and it stands as the roofline kernel. If they improve, the
// evict-first writeback path was the limiter.
//
// Indices are int32 on device (JAX demotes int64 without x64).

static constexpr int D_MODEL = 2048;
static constexpr int TOP_K   = 2;
static constexpr int VECS    = D_MODEL / 4;   // 512 float4 per row
static constexpr int NT      = 256;
static constexpr int ROWS_PER_BLK = 2;

__global__ __launch_bounds__(NT, 8)
void rb_dispatch_kernel(const float4* __restrict__ x,
                        const int* __restrict__ idx_s1,
                        const int* __restrict__ s1_to_s2,
                        float4* __restrict__ out,
                        int n_s2)
{
    const int row0 = blockIdx.x * ROWS_PER_BLK;
    const int row1 = row0 + 1;
    const int t = threadIdx.x;

    int e0 = (row0 < n_s2) ? idx_s1[s1_to_s2[row0]] : idx_s1[row0 - n_s2];
    int e1 = (row1 < n_s2) ? idx_s1[s1_to_s2[row1]] : idx_s1[row1 - n_s2];
    const int s0 = e0 / TOP_K;
    const int s1 = e1 / TOP_K;

    float4* __restrict__ dst0 = out + (long long)row0 * VECS;
    float4* __restrict__ dst1 = dst0 + VECS;

    const float4* __restrict__ src0 = x + (long long)s0 * VECS;

    if (s0 == s1) {
        float4 a0 = __ldg(&src0[t]);
        float4 a1 = __ldg(&src0[t + NT]);
        dst0[t]      = a0;
        dst0[t + NT] = a1;
        dst1[t]      = a0;
        dst1[t + NT] = a1;
    } else {
        const float4* __restrict__ src1 = x + (long long)s1 * VECS;
        float4 a0 = __ldg(&src0[t]);
        float4 a1 = __ldg(&src0[t + NT]);
        float4 b0 = __ldg(&src1[t]);
        float4 b1 = __ldg(&src1[t + NT]);
        dst0[t]      = a0;
        dst0[t + NT] = a1;
        dst1[t]      = b0;
        dst1[t + NT] = b1;
    }
}

extern "C" void kernel_launch(void* const* d_in, const int* in_sizes, int n_in,
                              void* d_out, int out_size)
{
    const float4* x        = (const float4*)d_in[0];
    const int*    idx_s1   = (const int*)d_in[1];
    const int*    s1_to_s2 = (const int*)d_in[2];

    const int n_s1 = in_sizes[1];        // 16384
    const int n_s2 = in_sizes[2];        // 8192
    const int n_out_rows = n_s1 + n_s2;  // 24576 (even)

    rb_dispatch_kernel<<<n_out_rows / ROWS_PER_BLK, NT>>>(
        x, idx_s1, s1_to_s2, (float4*)d_out, n_s2);
}

// round 16
// speedup vs baseline: 1.0054x; 1.0054x over previous
#include <cuda_runtime.h>
#include <cstdint>

// RBDispatcher — R15: last store-policy experiment = __stwt (write-through).
// Structure identical to R7 (best kernel, 41.6us).
//
//   out[r]        = x[ idx_s1[ s1_to_s2[r] ] / TOP_K ]   r in [0, N_S2)
//   out[N_S2 + i] = x[ idx_s1[i] / TOP_K ]               i in [0, N_S1)
//
// Evidence so far: every schedule (one-shot/persistent/MLP-2..8/dedup) and
// both prior store policies (default, .cs) plateau at 41.6-42.8us with DRAM
// ~67%. Both policies make each output line transit LTS twice (allocate +
// writeback), ~600MB of slice work. Write-through stores collapse that to
// one pass and keep L2 exclusively for x. If LTS double-transit is the
// residual binder -> ~37-40us; if the HBM write bus is the wall -> flat; if
// .wt breaks 128B write-combining -> regression (then R7 is final).
//
// Indices are int32 on device (JAX demotes int64 without x64).

static constexpr int D_MODEL = 2048;
static constexpr int TOP_K   = 2;
static constexpr int VECS    = D_MODEL / 4;   // 512 float4 per row
static constexpr int NT      = 256;
static constexpr int ROWS_PER_BLK = 2;

__global__ __launch_bounds__(NT, 8)
void rb_dispatch_kernel(const float4* __restrict__ x,
                        const int* __restrict__ idx_s1,
                        const int* __restrict__ s1_to_s2,
                        float4* __restrict__ out,
                        int n_s2)
{
    const int row0 = blockIdx.x * ROWS_PER_BLK;
    const int row1 = row0 + 1;
    const int t = threadIdx.x;

    int e0 = (row0 < n_s2) ? idx_s1[s1_to_s2[row0]] : idx_s1[row0 - n_s2];
    int e1 = (row1 < n_s2) ? idx_s1[s1_to_s2[row1]] : idx_s1[row1 - n_s2];
    const int s0 = e0 / TOP_K;
    const int s1 = e1 / TOP_K;

    float4* __restrict__ dst0 = out + (long long)row0 * VECS;
    float4* __restrict__ dst1 = dst0 + VECS;

    const float4* __restrict__ src0 = x + (long long)s0 * VECS;

    if (s0 == s1) {
        // Duplicate source (sorted s1 half): one read, two writes.
        float4 a0 = __ldg(&src0[t]);
        float4 a1 = __ldg(&src0[t + NT]);
        __stwt(&dst0[t],      a0);
        __stwt(&dst0[t + NT], a1);
        __stwt(&dst1[t],      a0);
        __stwt(&dst1[t + NT], a1);
    } else {
        const float4* __restrict__ src1 = x + (long long)s1 * VECS;
        // Batch all 4 loads, then all 4 stores.
        float4 a0 = __ldg(&src0[t]);
        float4 a1 = __ldg(&src0[t + NT]);
        float4 b0 = __ldg(&src1[t]);
        float4 b1 = __ldg(&src1[t + NT]);
        __stwt(&dst0[t],      a0);
        __stwt(&dst0[t + NT], a1);
        __stwt(&dst1[t],      b0);
        __stwt(&dst1[t + NT], b1);
    }
}

extern "C" void kernel_launch(void* const* d_in, const int* in_sizes, int n_in,
                              void* d_out, int out_size)
{
    const float4* x        = (const float4*)d_in[0];
    const int*    idx_s1   = (const int*)d_in[1];
    const int*    s1_to_s2 = (const int*)d_in[2];

    const int n_s1 = in_sizes[1];        // 16384
    const int n_s2 = in_sizes[2];        // 8192
    const int n_out_rows = n_s1 + n_s2;  // 24576 (even)

    rb_dispatch_kernel<<<n_out_rows / ROWS_PER_BLK, NT>>>(
        x, idx_s1, s1_to_s2, (float4*)d_out, n_s2);
}

// round 17
// speedup vs baseline: 1.0491x; 1.0435x over previous
#include <cuda_runtime.h>
#include <cstdint>

// RBDispatcher — R17: R7 core (best kernel, 41.6us) + temporally interleaved
// CTA->row mapping.
//
//   out[r]        = x[ idx_s1[ s1_to_s2[r] ] / TOP_K ]   r in [0, N_S2)
//   out[N_S2 + i] = x[ idx_s1[i] / TOP_K ]               i in [0, N_S1)
//
// Experiment matrix R3-R16 (schedule, MLP depth, grid shape, dedup, store
// policy .cs/.wt/default) plateaus at 41.6-42.8us ~= the effective ceiling
// for 201MB writes + gather reads. Last untested axis: the linear map runs
// all s2 pairs (random reads, DRAM refills) first, then all s1 pairs
// (sequential L2-friendly) -> coarse read/write phase alternation = worst
// case for DRAM bus turnaround. Interleave s2:s1 pairs 1:2 across the CTA
// sequence so the ~10% read-refill traffic is spread evenly.
//
// Indices are int32 on device (JAX demotes int64 without x64).

static constexpr int D_MODEL = 2048;
static constexpr int TOP_K   = 2;
static constexpr int VECS    = D_MODEL / 4;   // 512 float4 per row
static constexpr int NT      = 256;
static constexpr int ROWS_PER_BLK = 2;

__global__ __launch_bounds__(NT, 8)
void rb_dispatch_kernel(const float4* __restrict__ x,
                        const int* __restrict__ idx_s1,
                        const int* __restrict__ s1_to_s2,
                        float4* __restrict__ out,
                        int n_s2)
{
    const int t = threadIdx.x;

    // Interleave: groups of 3 CTAs = [1 s2-pair, 2 s1-pairs].
    //   n_s2 pairs = 4096, n_s1 pairs = 8192 -> 4096 groups of 3.
    const int g = blockIdx.x / 3;
    const int k = blockIdx.x - g * 3;
    int row0;
    if (k == 0) row0 = g * 2;                       // s2 pair g
    else        row0 = n_s2 + (g * 2 + (k - 1)) * 2; // s1 pairs 2g, 2g+1
    const int row1 = row0 + 1;

    int e0 = (row0 < n_s2) ? idx_s1[s1_to_s2[row0]] : idx_s1[row0 - n_s2];
    int e1 = (row1 < n_s2) ? idx_s1[s1_to_s2[row1]] : idx_s1[row1 - n_s2];
    const int s0 = e0 / TOP_K;
    const int s1 = e1 / TOP_K;

    float4* __restrict__ dst0 = out + (long long)row0 * VECS;
    float4* __restrict__ dst1 = dst0 + VECS;

    const float4* __restrict__ src0 = x + (long long)s0 * VECS;

    if (s0 == s1) {
        // Duplicate source (sorted s1 half): one read, two writes.
        float4 a0 = __ldg(&src0[t]);
        float4 a1 = __ldg(&src0[t + NT]);
        __stcs(&dst0[t],      a0);
        __stcs(&dst0[t + NT], a1);
        __stcs(&dst1[t],      a0);
        __stcs(&dst1[t + NT], a1);
    } else {
        const float4* __restrict__ src1 = x + (long long)s1 * VECS;
        // Batch all 4 loads, then all 4 stores.
        float4 a0 = __ldg(&src0[t]);
        float4 a1 = __ldg(&src0[t + NT]);
        float4 b0 = __ldg(&src1[t]);
        float4 b1 = __ldg(&src1[t + NT]);
        // Streaming stores keep x (64 MiB) L2-resident -> reads ~90% L2-hit.
        __stcs(&dst0[t],      a0);
        __stcs(&dst0[t + NT], a1);
        __stcs(&dst1[t],      b0);
        __stcs(&dst1[t + NT], b1);
    }
}

extern "C" void kernel_launch(void* const* d_in, const int* in_sizes, int n_in,
                              void* d_out, int out_size)
{
    const float4* x        = (const float4*)d_in[0];
    const int*    idx_s1   = (const int*)d_in[1];
    const int*    s1_to_s2 = (const int*)d_in[2];

    const int n_s1 = in_sizes[1];        // 16384
    const int n_s2 = in_sizes[2];        // 8192
    const int n_out_rows = n_s1 + n_s2;  // 24576 (even)

    rb_dispatch_kernel<<<n_out_rows / ROWS_PER_BLK, NT>>>(
        x, idx_s1, s1_to_s2, (float4*)d_out, n_s2);
}